// round 3
// baseline (speedup 1.0000x reference)
#include <cuda_runtime.h>

// YOLOv1 loss, single fused kernel, GB300.
// Accumulators: [0]=cls, [1]=obj_conf, [2]=noobj, [3]=coord
__device__ double g_acc[4];            // zero-init at module load; reset by last CTA each replay
__device__ unsigned int g_ticket = 0;  // reset by last CTA each replay

#define CELLS 49
#define CH 30
#define PERB (CELLS * CH)      // 1470 floats per item per tensor
#define ITEMS 2                // batch items per CTA
#define NT 256                 // threads per CTA (128 per item)
#define TILE (PERB * ITEMS)    // 2940 floats = 11760 B, 16B-aligned per CTA

__global__ __launch_bounds__(NT) void yolo_loss_fused(
    const float* __restrict__ pred, const float* __restrict__ targ,
    float* __restrict__ out) {
    __shared__ float sp[TILE];
    __shared__ float st[TILE];
    __shared__ float bpx[ITEMS][98][4];   // pred obj boxes, xyxy (compacted)
    __shared__ float btx[ITEMS][98][4];   // target obj boxes, xyxy
    __shared__ short boxoff[ITEMS][98];   // smem float offset (within item) of each box
    __shared__ int   cnt[ITEMS];
    __shared__ float red[NT / 32][4];
    __shared__ int   is_last;

    const int b   = blockIdx.x;           // 2-item tile index
    const int tid = threadIdx.x;
    const int sub  = tid >> 7;            // which item in tile (0/1)
    const int stid = tid & 127;           // thread within item

    // ---- Phase A: cooperative LDG.128 load of the whole 2-item tile
    const float4* p4 = reinterpret_cast<const float4*>(pred + (size_t)b * TILE);
    const float4* t4 = reinterpret_cast<const float4*>(targ + (size_t)b * TILE);
    float4* sp4 = reinterpret_cast<float4*>(sp);
    float4* st4 = reinterpret_cast<float4*>(st);
    #pragma unroll
    for (int i = tid; i < TILE / 4; i += NT) {   // 735 float4 each, 3 iters
        sp4[i] = p4[i];
        st4[i] = t4[i];
    }
    if (tid < ITEMS) cnt[tid] = 0;
    if (tid == 0) is_last = 0;
    __syncthreads();

    // ---- Phase B: per-cell noobj + class; compact obj-box list with xyxy
    float noobj = 0.0f, cls = 0.0f;
    if (stid < CELLS) {
        const int base = sub * PERB + stid * CH;
        const float* pc = sp + base;
        const float* tc = st + base;
        if (tc[4] == 0.0f) {               // noobj cell
            const float d4 = pc[4] - tc[4];
            const float d9 = pc[9] - tc[9];
            noobj = d4 * d4 + d9 * d9;
        } else {                           // obj cell
            float s = 0.0f;
            #pragma unroll
            for (int c = 10; c < 30; c++) {
                const float d = pc[c] - tc[c];
                s += d * d;
            }
            cls = s;
            const int slot = atomicAdd(&cnt[sub], 1);
            #pragma unroll
            for (int k = 0; k < 2; k++) {
                const int j   = slot * 2 + k;
                const int off = stid * CH + k * 5;       // offset within item
                boxoff[sub][j] = (short)off;
                const float* pp = pc + k * 5;
                const float* tt = tc + k * 5;
                bpx[sub][j][0] = pp[0] - pp[2] * 0.5f;
                bpx[sub][j][1] = pp[1] - pp[3] * 0.5f;
                bpx[sub][j][2] = pp[0] + pp[2] * 0.5f;
                bpx[sub][j][3] = pp[1] + pp[3] * 0.5f;
                btx[sub][j][0] = tt[0] - tt[2] * 0.5f;
                btx[sub][j][1] = tt[1] - tt[3] * 0.5f;
                btx[sub][j][2] = tt[0] + tt[2] * 0.5f;
                btx[sub][j][3] = tt[1] + tt[3] * 0.5f;
            }
        }
    }
    __syncthreads();

    // ---- Phase C: cmask[j] = any obj pred box overlaps target box j.
    // iou > 0 <=> intersection > 0 (union always > 0 since w,h >= 0.05).
    const int nb = cnt[sub] * 2;
    float coord = 0.0f, objc = 0.0f;
    if (stid < nb) {
        const float tx0 = btx[sub][stid][0], ty0 = btx[sub][stid][1];
        const float tx1 = btx[sub][stid][2], ty1 = btx[sub][stid][3];
        bool hit = false;
        for (int i = 0; i < nb; i++) {
            const float w = fminf(bpx[sub][i][2], tx1) - fmaxf(bpx[sub][i][0], tx0);
            const float h = fminf(bpx[sub][i][3], ty1) - fmaxf(bpx[sub][i][1], ty0);
            if (w > 0.0f && h > 0.0f) { hit = true; break; }
        }
        if (hit) {
            const int off = sub * PERB + boxoff[sub][stid];
            const float dx = sp[off]     - st[off];
            const float dy = sp[off + 1] - st[off + 1];
            const float dw = sqrtf(sp[off + 2]) - sqrtf(st[off + 2]);
            const float dh = sqrtf(sp[off + 3]) - sqrtf(st[off + 3]);
            coord = dx * dx + dy * dy + dw * dw + dh * dh;
            const float dc = sp[off + 4] - st[off + 4];
            objc = dc * dc;
        }
    }

    // ---- Phase D: block reduce (cls, objc, noobj, coord)
    float v0 = cls, v1 = objc, v2 = noobj, v3 = coord;
    #pragma unroll
    for (int o = 16; o > 0; o >>= 1) {
        v0 += __shfl_down_sync(0xffffffffu, v0, o);
        v1 += __shfl_down_sync(0xffffffffu, v1, o);
        v2 += __shfl_down_sync(0xffffffffu, v2, o);
        v3 += __shfl_down_sync(0xffffffffu, v3, o);
    }
    const int lane = tid & 31, warp = tid >> 5;
    if (lane == 0) {
        red[warp][0] = v0; red[warp][1] = v1;
        red[warp][2] = v2; red[warp][3] = v3;
    }
    __syncthreads();
    if (tid < 4) {
        float s = 0.0f;
        #pragma unroll
        for (int w = 0; w < NT / 32; w++) s += red[w][tid];
        atomicAdd(&g_acc[tid], (double)s);
    }
    __threadfence();
    __syncthreads();

    // ---- Phase E: ticket; last CTA finalizes + resets state for next replay
    if (tid == 0) {
        const unsigned int old = atomicAdd(&g_ticket, 1u);
        if (old == gridDim.x - 1) is_last = 1;
    }
    __syncthreads();
    if (is_last && tid == 0) {
        // All other CTAs fenced their adds before incrementing the ticket.
        const double cls_s   = atomicAdd(&g_acc[0], 0.0);
        const double objc_s  = atomicAdd(&g_acc[1], 0.0);
        const double noobj_s = atomicAdd(&g_acc[2], 0.0);
        const double coord_s = atomicAdd(&g_acc[3], 0.0);
        const double invB = 1.0 / (double)(gridDim.x * ITEMS);
        const float bcls   = (float)(cls_s * invB);
        const float bobj   = (float)((objc_s + 0.5 * noobj_s) * invB);
        const float bcoord = (float)(coord_s * 5.0 * invB);
        out[0] = bcls + bobj + bcoord;
        out[1] = bcls;
        out[2] = bobj;
        out[3] = bcoord;
        // reset for next graph replay
        g_acc[0] = 0.0; g_acc[1] = 0.0; g_acc[2] = 0.0; g_acc[3] = 0.0;
        __threadfence();
        g_ticket = 0u;
    }
}

extern "C" void kernel_launch(void* const* d_in, const int* in_sizes, int n_in,
                              void* d_out, int out_size) {
    const float* pred = (const float*)d_in[0];
    const float* targ = (const float*)d_in[1];
    float* out = (float*)d_out;
    const int B = in_sizes[0] / PERB;        // 8192
    yolo_loss_fused<<<B / ITEMS, NT>>>(pred, targ, out);
}